// round 17
// baseline (speedup 1.0000x reference)
#include <cuda_runtime.h>
#include <math.h>
#include <stdint.h>

#define SLOPE 0.2f
#define NB   32
#define TT   1002
#define DD   16
#define EE   32
#define HH   64
#define LEN  1000
#define NN   (NB*LEN)
#define TPB  320
#define MTILE 320

#define RSA   68      // fp32 A row stride: 68 % 32 == 4 -> conflict-free frag loads

// ---- smem layout ----
// floats: A [0, 21760), W0p [21760, 26880), W1p [26880, 35072), W2p [35072, 43264), misc
#define OFF_A    0
#define W0Q      5440          // uint4 index of W0 packed (float idx 21760 / 4)
#define W1Q      6720          // 26880 / 4
#define W2Q      8768          // 35072 / 4
#define MF_B0    43264
#define MF_B1    43328
#define MF_B2    43392
#define MF_WO    43456
#define MF_W0E   43520
#define SMEM_FLOATS 43584
#define SMEM_BYTES  (SMEM_FLOATS * 4)    // 174336

__device__ float g_logscratch[NN * DD];

static __device__ __forceinline__ void tf32_split(float x, uint32_t& hi, uint32_t& lo) {
    uint32_t h;
    asm("cvt.rna.tf32.f32 %0, %1;" : "=r"(h) : "f"(x));
    float rem = x - __uint_as_float(h);
    uint32_t l;
    asm("cvt.rna.tf32.f32 %0, %1;" : "=r"(l) : "f"(rem));
    hi = h; lo = l;
}

// D += A(16x8) * B(8x8), tf32 inputs, f32 accumulate
static __device__ __forceinline__ void mma8(float c[4], const uint32_t a[4], const uint32_t b[2]) {
    asm volatile(
        "mma.sync.aligned.m16n8k8.row.col.f32.tf32.tf32.f32 "
        "{%0,%1,%2,%3},{%4,%5,%6,%7},{%8,%9},{%0,%1,%2,%3};"
        : "+f"(c[0]), "+f"(c[1]), "+f"(c[2]), "+f"(c[3])
        : "r"(a[0]), "r"(a[1]), "r"(a[2]), "r"(a[3]), "r"(b[0]), "r"(b[1]));
}

// one 3xTF32 GEMM round. A: fp32 in smem (split at load); B: frag-packed uint4s.
template<int NK>
static __device__ __forceinline__ void mma_round(
    const float* __restrict__ smf, const uint4* __restrict__ wq,
    int lane, int wrow, float acc[2][8][4])
{
    #pragma unroll
    for (int m = 0; m < 2; m++)
        #pragma unroll
        for (int n = 0; n < 8; n++)
            #pragma unroll
            for (int q = 0; q < 4; q++) acc[m][n][q] = 0.f;

    const int r0 = lane >> 2, c0 = lane & 3;
    #pragma unroll
    for (int k = 0; k < NK; k++) {
        uint32_t ah[2][4], al[2][4];
        #pragma unroll
        for (int m = 0; m < 2; m++)
            #pragma unroll
            for (int q = 0; q < 4; q++) {
                int idx = (wrow + m*16 + r0 + ((q & 1) << 3)) * RSA
                        + k*8 + c0 + ((q >> 1) << 2);
                tf32_split(smf[idx], ah[m][q], al[m][q]);
            }
        #pragma unroll
        for (int n = 0; n < 8; n++) {
            uint4 b = wq[(k*8 + n)*32 + lane];
            uint32_t bh[2] = {b.x, b.y};
            uint32_t bl[2] = {b.z, b.w};
            mma8(acc[0][n], ah[0], bh);
            mma8(acc[1][n], ah[1], bh);
            mma8(acc[0][n], ah[0], bl);
            mma8(acc[1][n], ah[1], bl);
            mma8(acc[0][n], al[0], bh);
            mma8(acc[1][n], al[1], bh);
        }
    }
}

// pack one weight matrix into fragment order:
// wq[(k*8+n)*32 + lane] = {hi(W[n8+r0][k8+c0]), hi(W[n8+r0][k8+c0+4]),
//                          lo(...c0),           lo(...c0+4)}
template<int NK, bool IS_W0>
static __device__ __forceinline__ void pack_weight(
    uint4* __restrict__ wq, const float* __restrict__ wg, int tid)
{
    for (int idx = tid; idx < NK * 8 * 32; idx += TPB) {
        int lane = idx & 31, n = (idx >> 5) & 7, k = idx >> 8;
        int rr = n*8 + (lane >> 2);
        int cb = k*8 + (lane & 3);
        float v0, v1;
        if (IS_W0) {
            v0 = (cb     < 33) ? wg[rr * 33 + cb]     : 0.f;
            v1 = (cb + 4 < 33) ? wg[rr * 33 + cb + 4] : 0.f;
        } else {
            v0 = wg[rr * HH + cb];
            v1 = wg[rr * HH + cb + 4];
        }
        uint32_t h0, l0, h1, l1;
        tf32_split(v0, h0, l0);
        tf32_split(v1, h1, l1);
        wq[idx] = make_uint4(h0, h1, l0, l1);
    }
}

__global__ __launch_bounds__(TPB)
void mlp_hmma_kernel(
    const float* __restrict__ x,   const float* __restrict__ emb,
    const float* __restrict__ W0,  const float* __restrict__ b0,
    const float* __restrict__ W1,  const float* __restrict__ b1,
    const float* __restrict__ W2,  const float* __restrict__ b2,
    const float* __restrict__ Wo,  const float* __restrict__ bo,
    float* __restrict__ out_res)
{
    extern __shared__ __align__(16) float sm[];
    uint4* smq = (uint4*)sm;

    const int d    = blockIdx.y;
    const int tid  = threadIdx.x;
    const int lane = tid & 31;
    const int wid  = tid >> 5;
    const int n0   = blockIdx.x * MTILE;
    const int wrow = wid * 32;

    // ================= staging =================
    {
        const float* w0g = W0 + (size_t)d * HH * (EE + 1);
        pack_weight<5, true >(smq + W0Q, w0g, tid);
        pack_weight<8, false>(smq + W1Q, W1 + (size_t)d * HH * HH, tid);
        pack_weight<8, false>(smq + W2Q, W2 + (size_t)d * HH * HH, tid);
        if (tid < HH) {
            sm[MF_B0  + tid] = b0[d * HH + tid];
            sm[MF_B1  + tid] = b1[d * HH + tid];
            sm[MF_B2  + tid] = b2[d * HH + tid];
            sm[MF_WO  + tid] = Wo[d * HH + tid];
            sm[MF_W0E + tid] = w0g[tid * 33 + 32];
        }

        // A: fp32, row=tid; cols 0..31 = emb, 32 = x_t, 33..39 = 0
        int n = n0 + tid, bb = n / LEN;
        int row = bb * TT + (n - bb * LEN) + 2;        // LAGS = 2
        const float4* ev = (const float4*)(emb + (size_t)row * EE);
        float4* ar = (float4*)(sm + OFF_A + tid * RSA);
        #pragma unroll
        for (int q8 = 0; q8 < 8; q8++) ar[q8] = ev[q8];
        sm[OFF_A + tid*RSA + 32] = x[(size_t)row * DD + d];
        #pragma unroll
        for (int j = 33; j < 40; j++) sm[OFF_A + tid*RSA + j] = 0.f;
    }
    __syncthreads();

    const int r0 = lane >> 2, c0 = lane & 3;
    float acc[2][8][4];
    unsigned g0[2] = {0,0}, g1[2] = {0,0}, g2[2] = {0,0};
    float2 bias2[8];

    // ================= forward layer 0 =================
    mma_round<5>(sm + OFF_A, smq + W0Q, lane, wrow, acc);
    #pragma unroll
    for (int n = 0; n < 8; n++) bias2[n] = *(const float2*)&sm[MF_B0 + n*8 + 2*c0];
    #pragma unroll
    for (int m = 0; m < 2; m++)
        #pragma unroll
        for (int n = 0; n < 8; n++)
            #pragma unroll
            for (int q = 0; q < 4; q++) {
                int row = wrow + m*16 + r0 + ((q >> 1) << 3);
                int col = n*8 + 2*c0 + (q & 1);
                float z = acc[m][n][q] + ((q & 1) ? bias2[n].y : bias2[n].x);
                unsigned g = (z >= 0.f);
                g0[m] |= g << (n*4 + q);
                sm[OFF_A + row*RSA + col] = g ? z : z * SLOPE;
            }
    __syncwarp();

    // ================= forward layer 1 =================
    mma_round<8>(sm + OFF_A, smq + W1Q, lane, wrow, acc);
    #pragma unroll
    for (int n = 0; n < 8; n++) bias2[n] = *(const float2*)&sm[MF_B1 + n*8 + 2*c0];
    #pragma unroll
    for (int m = 0; m < 2; m++)
        #pragma unroll
        for (int n = 0; n < 8; n++)
            #pragma unroll
            for (int q = 0; q < 4; q++) {
                int row = wrow + m*16 + r0 + ((q >> 1) << 3);
                int col = n*8 + 2*c0 + (q & 1);
                float z = acc[m][n][q] + ((q & 1) ? bias2[n].y : bias2[n].x);
                unsigned g = (z >= 0.f);
                g1[m] |= g << (n*4 + q);
                sm[OFF_A + row*RSA + col] = g ? z : z * SLOPE;
            }
    __syncwarp();

    // ================= forward layer 2 + residual head =================
    mma_round<8>(sm + OFF_A, smq + W2Q, lane, wrow, acc);
    #pragma unroll
    for (int n = 0; n < 8; n++) bias2[n] = *(const float2*)&sm[MF_B2 + n*8 + 2*c0];
    float2 wo2[8];
    #pragma unroll
    for (int n = 0; n < 8; n++) wo2[n] = *(const float2*)&sm[MF_WO + n*8 + 2*c0];
    {
        float p[4] = {0.f, 0.f, 0.f, 0.f};
        #pragma unroll
        for (int m = 0; m < 2; m++)
            #pragma unroll
            for (int n = 0; n < 8; n++)
                #pragma unroll
                for (int q = 0; q < 4; q++) {
                    float z = acc[m][n][q] + ((q & 1) ? bias2[n].y : bias2[n].x);
                    unsigned g = (z >= 0.f);
                    g2[m] |= g << (n*4 + q);
                    float a = g ? z : z * SLOPE;
                    p[m*2 + (q >> 1)] += a * ((q & 1) ? wo2[n].y : wo2[n].x);
                }
        #pragma unroll
        for (int i = 0; i < 4; i++) {
            p[i] += __shfl_xor_sync(0xffffffffu, p[i], 1);
            p[i] += __shfl_xor_sync(0xffffffffu, p[i], 2);
        }
        if (c0 == 0) {
            float bb = bo[d];
            #pragma unroll
            for (int m = 0; m < 2; m++)
                #pragma unroll
                for (int rh = 0; rh < 2; rh++) {
                    int row = wrow + m*16 + r0 + rh*8;
                    out_res[(size_t)(n0 + row) * DD + d] = bb + p[m*2 + rh];
                }
        }
    }

    // ================= tangent seed: t0 = g0 * W0[:,E] =================
    #pragma unroll
    for (int m = 0; m < 2; m++)
        #pragma unroll
        for (int n = 0; n < 8; n++)
            #pragma unroll
            for (int q = 0; q < 4; q++) {
                int row = wrow + m*16 + r0 + ((q >> 1) << 3);
                int col = n*8 + 2*c0 + (q & 1);
                float w = sm[MF_W0E + col];
                sm[OFF_A + row*RSA + col] =
                    (((g0[m] >> (n*4 + q)) & 1u) ? 1.f : SLOPE) * w;
            }
    __syncwarp();

    // ================= tangent layer 1: t1 = g1*(W1 @ t0) =================
    mma_round<8>(sm + OFF_A, smq + W1Q, lane, wrow, acc);
    #pragma unroll
    for (int m = 0; m < 2; m++)
        #pragma unroll
        for (int n = 0; n < 8; n++)
            #pragma unroll
            for (int q = 0; q < 4; q++) {
                int row = wrow + m*16 + r0 + ((q >> 1) << 3);
                int col = n*8 + 2*c0 + (q & 1);
                sm[OFF_A + row*RSA + col] =
                    (((g1[m] >> (n*4 + q)) & 1u) ? 1.f : SLOPE) * acc[m][n][q];
            }
    __syncwarp();

    // ================= tangent layer 2 + Jacobian head =================
    mma_round<8>(sm + OFF_A, smq + W2Q, lane, wrow, acc);
    {
        float p[4] = {0.f, 0.f, 0.f, 0.f};
        #pragma unroll
        for (int m = 0; m < 2; m++)
            #pragma unroll
            for (int n = 0; n < 8; n++)
                #pragma unroll
                for (int q = 0; q < 4; q++) {
                    float t = (((g2[m] >> (n*4 + q)) & 1u) ? 1.f : SLOPE) * acc[m][n][q];
                    p[m*2 + (q >> 1)] += t * ((q & 1) ? wo2[n].y : wo2[n].x);
                }
        #pragma unroll
        for (int i = 0; i < 4; i++) {
            p[i] += __shfl_xor_sync(0xffffffffu, p[i], 1);
            p[i] += __shfl_xor_sync(0xffffffffu, p[i], 2);
        }
        if (c0 == 0) {
            #pragma unroll
            for (int m = 0; m < 2; m++)
                #pragma unroll
                for (int rh = 0; rh < 2; rh++) {
                    int row = wrow + m*16 + r0 + rh*8;
                    g_logscratch[(size_t)(n0 + row) * DD + d] = logf(fabsf(p[m*2 + rh]));
                }
        }
    }
}

// deterministic fixed-order reduction over d for log|det J|
__global__ void logdet_reduce_kernel(float* __restrict__ out_log)
{
    int n = blockIdx.x * 256 + threadIdx.x;
    if (n >= NN) return;
    const float4* p = reinterpret_cast<const float4*>(&g_logscratch[(size_t)n * DD]);
    float s = 0.f;
    #pragma unroll
    for (int i = 0; i < DD / 4; i++) {
        float4 v4 = p[i];
        s += v4.x; s += v4.y; s += v4.z; s += v4.w;
    }
    out_log[n] = s;
}

extern "C" void kernel_launch(void* const* d_in, const int* in_sizes, int n_in,
                              void* d_out, int out_size)
{
    const float* x   = (const float*)d_in[0];
    const float* emb = (const float*)d_in[1];
    const float* W0  = (const float*)d_in[2];
    const float* b0  = (const float*)d_in[3];
    const float* W1  = (const float*)d_in[4];
    const float* b1  = (const float*)d_in[5];
    const float* W2  = (const float*)d_in[6];
    const float* b2  = (const float*)d_in[7];
    const float* Wo  = (const float*)d_in[8];
    const float* bo  = (const float*)d_in[9];

    float* out_res = (float*)d_out;            // [N, D]
    float* out_log = (float*)d_out + NN * DD;  // [N]

    cudaFuncSetAttribute(mlp_hmma_kernel,
                         cudaFuncAttributeMaxDynamicSharedMemorySize, SMEM_BYTES);

    dim3 grid(NN / MTILE, DD);   // 100 x 16
    mlp_hmma_kernel<<<grid, TPB, SMEM_BYTES>>>(x, emb, W0, b0, W1, b1, W2, b2, Wo, bo, out_res);
    logdet_reduce_kernel<<<(NN + 255) / 256, 256>>>(out_log);
}